// round 14
// baseline (speedup 1.0000x reference)
#include <cuda_runtime.h>
#include <cuda_bf16.h>
#include <cstdint>
#include <stdint.h>
#include <math.h>

#define Bb 16
#define Nn 1024
#define Dd 512
#define Kk 8
#define NITER 3
#define NCHB 8           // row-chunks per batch in persistent kernel (128 rows each)

#define Mtot (Bb*Nn)     // 16384
#define Ntot (2*Dd)      // 1024
#define LDA 40           // smem row stride (bf16): 32 + 8 pad, conflict-free ldmatrix
#define TILE_B (128*LDA*2)    // 10240 bytes
#define MMA_SMEM (2*4*TILE_B) // 81920
#define NBLK (Bb*NCHB)   // 128 persistent blocks (<=148 SMs -> all wave-1 resident)

__device__ __constant__ float c_EPS = 1e-8f;
__device__ __constant__ float c_LNEPS = 1e-5f;
__device__ __constant__ float c_LOG2PI = 1.8378770664093453f;

// ---------------- scratch ----------------------------------------------------
__device__ float g_keys[Mtot*Dd];
__device__ float g_values[Mtot*Dd];
__device__ float g_q[Bb*Kk*Dd];
__device__ float g_sigma[Bb*Kk*Dd];
__device__ float2 g_wq[Bb*Kk*Dd];          // interleaved {w, q*w}
__device__ float g_c1[Bb*Kk];
__device__ float g_mixing[Bb*Kk];
__device__ float g_attn[Bb*Nn*Kk];
__device__ float g_Spart[Bb*NCHB*Kk];
__device__ float g_mupart[NCHB*Bb*Kk*Dd];
__device__ float g_v2part[NCHB*Bb*Kk*Dd];

__device__ __align__(16) __nv_bfloat16 g_Ahi[Mtot*Dd];
__device__ __align__(16) __nv_bfloat16 g_Alo[Mtot*Dd];
__device__ __align__(16) __nv_bfloat16 g_Bhi[Ntot*Dd];
__device__ __align__(16) __nv_bfloat16 g_Blo[Ntot*Dd];

// global barrier state (sense-reversing; gen monotonically increases)
__device__ unsigned g_count = 0;
__device__ volatile unsigned g_gen = 0;

__device__ __forceinline__ void gbar() {
    __syncthreads();
    if (threadIdx.x == 0) {
        __threadfence();
        unsigned g = g_gen;
        if (atomicAdd(&g_count, 1u) == NBLK - 1u) {
            g_count = 0;
            __threadfence();
            g_gen = g + 1u;
        } else {
            while (g_gen == g) { }
            __threadfence();
        }
    }
    __syncthreads();
}

// ---------------- PTX helpers ------------------------------------------------
__device__ __forceinline__ uint32_t smem_u32(const void* p) {
    uint32_t a;
    asm("{ .reg .u64 t; cvta.to.shared.u64 t, %1; cvt.u32.u64 %0, t; }" : "=r"(a) : "l"(p));
    return a;
}
__device__ __forceinline__ void cpasync16(uint32_t saddr, const void* g) {
    asm volatile("cp.async.ca.shared.global [%0], [%1], 16;" :: "r"(saddr), "l"(g));
}
__device__ __forceinline__ void ldm4(uint32_t* r, uint32_t addr) {
    asm volatile("ldmatrix.sync.aligned.m8n8.x4.shared.b16 {%0,%1,%2,%3}, [%4];"
        : "=r"(r[0]), "=r"(r[1]), "=r"(r[2]), "=r"(r[3]) : "r"(addr));
}
__device__ __forceinline__ void mma16816(float* c, const uint32_t* a, const uint32_t* b) {
    asm volatile(
        "mma.sync.aligned.m16n8k16.row.col.f32.bf16.bf16.f32 "
        "{%0,%1,%2,%3}, {%4,%5,%6,%7}, {%8,%9}, {%0,%1,%2,%3};"
        : "+f"(c[0]), "+f"(c[1]), "+f"(c[2]), "+f"(c[3])
        : "r"(a[0]), "r"(a[1]), "r"(a[2]), "r"(a[3]), "r"(b[0]), "r"(b[1]));
}

// ---------------- K0: LN stats + bf16 hi/lo split ----------------------------
__global__ __launch_bounds__(128) void ln_split(
    const float* __restrict__ E, const float* __restrict__ lng, const float* __restrict__ lnb)
{
    int row = blockIdx.x;
    int t = threadIdx.x;
    float4 v = ((const float4*)(E + (size_t)row * Dd))[t];
    float s = v.x + v.y + v.z + v.w;
    float s2 = v.x*v.x + v.y*v.y + v.z*v.z + v.w*v.w;
    #pragma unroll
    for (int o = 16; o; o >>= 1) {
        s  += __shfl_xor_sync(0xffffffffu, s,  o);
        s2 += __shfl_xor_sync(0xffffffffu, s2, o);
    }
    __shared__ float sh[2][4];
    if ((t & 31) == 0) { sh[0][t >> 5] = s; sh[1][t >> 5] = s2; }
    __syncthreads();
    float S  = sh[0][0] + sh[0][1] + sh[0][2] + sh[0][3];
    float S2 = sh[1][0] + sh[1][1] + sh[1][2] + sh[1][3];
    float m = S / (float)Dd;
    float var = S2 / (float)Dd - m * m;
    float rs = rsqrtf(var + c_LNEPS);

    float4 g4 = ((const float4*)lng)[t];
    float4 b4 = ((const float4*)lnb)[t];
    float y[4];
    y[0] = (v.x - m) * rs * g4.x + b4.x;
    y[1] = (v.y - m) * rs * g4.y + b4.y;
    y[2] = (v.z - m) * rs * g4.z + b4.z;
    y[3] = (v.w - m) * rs * g4.w + b4.w;
    __nv_bfloat16 hi[4], lo[4];
    #pragma unroll
    for (int i = 0; i < 4; i++) {
        hi[i] = __float2bfloat16(y[i]);
        lo[i] = __float2bfloat16(y[i] - __bfloat162float(hi[i]));
    }
    *(uint2*)(g_Ahi + (size_t)row * Dd + t * 4) = *(uint2*)hi;
    *(uint2*)(g_Alo + (size_t)row * Dd + t * 4) = *(uint2*)lo;
}

// ---------------- K1: W^T bf16 hi/lo split -----------------------------------
__global__ void wt_split(const float* __restrict__ Wk, const float* __restrict__ Wv) {
    __shared__ float tile[32][33];
    int n0 = blockIdx.x * 32;
    int k0 = blockIdx.y * 32;
    const float* W = (n0 < Dd) ? Wk : Wv;
    int nc0 = n0 & (Dd - 1);
    int tx = threadIdx.x, ty = threadIdx.y;
    #pragma unroll
    for (int i = ty; i < 32; i += 8)
        tile[i][tx] = W[(size_t)(k0 + i) * Dd + nc0 + tx];
    __syncthreads();
    #pragma unroll
    for (int i = ty; i < 32; i += 8) {
        float x = tile[tx][i];
        __nv_bfloat16 hi = __float2bfloat16(x);
        __nv_bfloat16 lo = __float2bfloat16(x - __bfloat162float(hi));
        g_Bhi[(size_t)(n0 + i) * Dd + k0 + tx] = hi;
        g_Blo[(size_t)(n0 + i) * Dd + k0 + tx] = lo;
    }
}

// ---------------- K2: HMMA bf16x3 GEMM (unchanged; ~170us) -------------------
__global__ __launch_bounds__(256, 2) void mma_kv(
    const float* __restrict__ bk, const float* __restrict__ bv)
{
    extern __shared__ char dsm[];
    int tid = threadIdx.x, lane = tid & 31, wid = tid >> 5;
    int warp_m = wid >> 1, warp_n = wid & 1;
    int n0 = blockIdx.x * 128;
    int m0 = blockIdx.y * 128;

    float acc[2][8][4];
    #pragma unroll
    for (int i = 0; i < 2; i++)
        #pragma unroll
        for (int j = 0; j < 8; j++)
            #pragma unroll
            for (int q = 0; q < 4; q++) acc[i][j][q] = 0.f;

    const int lrow = tid >> 1;
    const int lseg = (tid & 1) * 2;

    #pragma unroll
    for (int j = 0; j < 2; j++) {
        int off = (lseg + j) * 8;
        size_t ao = (size_t)(m0 + lrow) * Dd + off;
        size_t bo = (size_t)(n0 + lrow) * Dd + off;
        uint32_t so = lrow * LDA * 2 + off * 2;
        cpasync16(smem_u32(dsm + 0*TILE_B + so), g_Ahi + ao);
        cpasync16(smem_u32(dsm + 1*TILE_B + so), g_Alo + ao);
        cpasync16(smem_u32(dsm + 2*TILE_B + so), g_Bhi + bo);
        cpasync16(smem_u32(dsm + 3*TILE_B + so), g_Blo + bo);
    }
    asm volatile("cp.async.commit_group;" ::: "memory");

    for (int kc = 0; kc < 16; kc++) {
        int buf = kc & 1;
        char* cur = dsm + buf * 4 * TILE_B;
        if (kc < 15) {
            char* nxt = dsm + (buf ^ 1) * 4 * TILE_B;
            int kn = (kc + 1) * 32;
            #pragma unroll
            for (int j = 0; j < 2; j++) {
                int off = (lseg + j) * 8;
                size_t ao = (size_t)(m0 + lrow) * Dd + kn + off;
                size_t bo = (size_t)(n0 + lrow) * Dd + kn + off;
                uint32_t so = lrow * LDA * 2 + off * 2;
                cpasync16(smem_u32(nxt + 0*TILE_B + so), g_Ahi + ao);
                cpasync16(smem_u32(nxt + 1*TILE_B + so), g_Alo + ao);
                cpasync16(smem_u32(nxt + 2*TILE_B + so), g_Bhi + bo);
                cpasync16(smem_u32(nxt + 3*TILE_B + so), g_Blo + bo);
            }
            asm volatile("cp.async.commit_group;" ::: "memory");
            asm volatile("cp.async.wait_group 1;" ::: "memory");
        } else {
            asm volatile("cp.async.wait_group 0;" ::: "memory");
        }
        __syncthreads();

        const __nv_bfloat16* sAhi = (const __nv_bfloat16*)(cur + 0*TILE_B);
        const __nv_bfloat16* sAlo = (const __nv_bfloat16*)(cur + 1*TILE_B);
        const __nv_bfloat16* sBhi = (const __nv_bfloat16*)(cur + 2*TILE_B);
        const __nv_bfloat16* sBlo = (const __nv_bfloat16*)(cur + 3*TILE_B);

        #pragma unroll
        for (int ks = 0; ks < 2; ks++) {
            uint32_t ahi[2][4], alo[2][4];
            #pragma unroll
            for (int mi = 0; mi < 2; mi++) {
                int row = warp_m * 32 + mi * 16 + (lane & 15);
                int col = ks * 16 + (lane >> 4) * 8;
                ldm4(ahi[mi], smem_u32(&sAhi[row * LDA + col]));
                ldm4(alo[mi], smem_u32(&sAlo[row * LDA + col]));
            }
            #pragma unroll
            for (int h = 0; h < 2; h++) {
                uint32_t bhi[4][2], blo[4][2];
                #pragma unroll
                for (int jj = 0; jj < 2; jj++) {
                    int nrow = warp_n * 64 + h * 32 + jj * 16 + (lane & 7) + ((lane >> 4) << 3);
                    int col = ks * 16 + ((lane >> 3) & 1) * 8;
                    uint32_t r4[4];
                    ldm4(r4, smem_u32(&sBhi[nrow * LDA + col]));
                    bhi[2*jj][0] = r4[0]; bhi[2*jj][1] = r4[1];
                    bhi[2*jj+1][0] = r4[2]; bhi[2*jj+1][1] = r4[3];
                    ldm4(r4, smem_u32(&sBlo[nrow * LDA + col]));
                    blo[2*jj][0] = r4[0]; blo[2*jj][1] = r4[1];
                    blo[2*jj+1][0] = r4[2]; blo[2*jj+1][1] = r4[3];
                }
                #pragma unroll
                for (int mi = 0; mi < 2; mi++)
                    #pragma unroll
                    for (int j2 = 0; j2 < 4; j2++) {
                        int nj = h * 4 + j2;
                        mma16816(acc[mi][nj], ahi[mi], bhi[j2]);
                        mma16816(acc[mi][nj], ahi[mi], blo[j2]);
                        mma16816(acc[mi][nj], alo[mi], bhi[j2]);
                    }
            }
        }
        __syncthreads();
    }

    const bool isK = (n0 < Dd);
    float* Dst = isK ? g_keys : g_values;
    const float* bias = isK ? bk : bv;
    int nbase = (isK ? n0 : n0 - Dd) + warp_n * 64;
    int mbase = m0 + warp_m * 32;
    int r = lane >> 2, cp = 2 * (lane & 3);
    #pragma unroll
    for (int mi = 0; mi < 2; mi++) {
        #pragma unroll
        for (int nj = 0; nj < 8; nj++) {
            int n = nbase + nj * 8 + cp;
            float b0 = bias[n], b1 = bias[n + 1];
            int m = mbase + mi * 16 + r;
            float2 o0 = { acc[mi][nj][0] + b0, acc[mi][nj][1] + b1 };
            float2 o1 = { acc[mi][nj][2] + b0, acc[mi][nj][3] + b1 };
            *(float2*)&Dst[(size_t)m * Dd + n] = o0;
            *(float2*)&Dst[(size_t)(m + 8) * Dd + n] = o1;
        }
    }
}

// ---------------- K3: slots, queries, AND iter-0 prep (w/qw/c1) --------------
__global__ void init_slots_queries(
    const float* __restrict__ noise_init, const float* __restrict__ slots_mu,
    const float* __restrict__ slots_ls,   const float* __restrict__ mix_in,
    const float* __restrict__ Wq,         const float* __restrict__ bq)
{
    int bk_ = blockIdx.x;
    int b = bk_ >> 3, k = bk_ & 7;
    __shared__ float slot[Dd];
    int t = threadIdx.x;
    for (int d = t; d < Dd; d += 128) {
        float sg = expf(slots_ls[k * Dd + d]);
        slot[d] = slots_mu[k * Dd + d] + sg * noise_init[((size_t)b * Kk + k) * Dd + d];
        g_sigma[((size_t)b * Kk + k) * Dd + d] = sg;
    }
    if (t == 0) g_mixing[b * Kk + k] = mix_in[k];
    __syncthreads();
    float slog = 0.f, sqwq = 0.f;
    for (int j = t; j < Dd; j += 128) {
        float acc = bq[j];
        for (int d = 0; d < Dd; d++) acc += slot[d] * Wq[(size_t)d * Dd + j];
        g_q[((size_t)bk_) * Dd + j] = acc;
        float sg = g_sigma[(size_t)bk_ * Dd + j];
        float w = 1.f / (sg * sg + c_EPS);
        g_wq[(size_t)bk_ * Dd + j] = make_float2(w, acc * w);
        slog += logf(fabsf(sg) + c_EPS);
        sqwq += acc * acc * w;
    }
    #pragma unroll
    for (int o = 16; o; o >>= 1) {
        slog += __shfl_xor_sync(0xffffffffu, slog, o);
        sqwq += __shfl_xor_sync(0xffffffffu, sqwq, o);
    }
    __shared__ float sh[2][4];
    if ((t & 31) == 0) { sh[0][t >> 5] = slog; sh[1][t >> 5] = sqwq; }
    __syncthreads();
    if (t == 0) {
        float SL = sh[0][0] + sh[0][1] + sh[0][2] + sh[0][3];
        float SQ = sh[1][0] + sh[1][1] + sh[1][2] + sh[1][3];
        g_c1[bk_] = -0.5f * (float)Dd * c_LOG2PI - 0.5f * SL - 0.5f * SQ;
    }
}

// ---------------- K4: persistent EM loop (all 3 iterations, 1 launch) --------
// grid (Bb, NCHB) = 128 blocks, 256 thr. Block (b,y): rows [y*128, y*128+128),
// and doubles as reducer for slot (b, k=y).
__global__ __launch_bounds__(256) void em_persist(
    const float* __restrict__ noise_final, float* __restrict__ out)
{
    int b = blockIdx.x, y = blockIdx.y;
    int t = threadIdx.x, warp = t >> 5, lane = t & 31;
    __shared__ float2 swq[Kk * Dd];          // 32KB
    __shared__ float satt[128][Kk];          // 4KB
    __shared__ float wcs[8][Kk];
    __shared__ float c1s[Kk], mixs[Kk];
    __shared__ float sh[2][8];

    const int rb = y * 128;                  // block's first row
    const int bk_ = b * Kk + y;              // reducer identity (k = y)

    for (int it = 0; it < NITER; it++) {
        // ---- load per-iteration tables ----
        for (int i = t; i < Kk * Dd; i += 256)
            swq[i] = g_wq[(size_t)b * Kk * Dd + i];
        if (t < Kk) { c1s[t] = g_c1[b * Kk + t]; mixs[t] = g_mixing[b * Kk + t]; }
        __syncthreads();

        // ---- Phase A: attn for 128 rows; warp owns 16 rows (4 groups of 4) ----
        float cs = 0.f;
        for (int g = 0; g < 4; g++) {
            int r0 = rb + warp * 16 + g * 4;
            const float* kb = g_keys + ((size_t)b * Nn + r0) * Dd;
            float acc[4][Kk];
            #pragma unroll
            for (int r = 0; r < 4; r++)
                #pragma unroll
                for (int k = 0; k < Kk; k++) acc[r][k] = 0.f;
            #pragma unroll
            for (int i = 0; i < 16; i++) {
                int d = lane + 32 * i;
                float kv0 = kb[d], kv1 = kb[Dd + d], kv2 = kb[2*Dd + d], kv3 = kb[3*Dd + d];
                float h0 = -0.5f*kv0*kv0, h1 = -0.5f*kv1*kv1, h2 = -0.5f*kv2*kv2, h3 = -0.5f*kv3*kv3;
                #pragma unroll
                for (int k = 0; k < Kk; k++) {
                    float2 wq = swq[k * Dd + d];
                    acc[0][k] = fmaf(kv0, wq.y, fmaf(h0, wq.x, acc[0][k]));
                    acc[1][k] = fmaf(kv1, wq.y, fmaf(h1, wq.x, acc[1][k]));
                    acc[2][k] = fmaf(kv2, wq.y, fmaf(h2, wq.x, acc[2][k]));
                    acc[3][k] = fmaf(kv3, wq.y, fmaf(h3, wq.x, acc[3][k]));
                }
            }
            #pragma unroll
            for (int o = 16; o; o >>= 1)
                #pragma unroll
                for (int r = 0; r < 4; r++)
                    #pragma unroll
                    for (int k = 0; k < Kk; k++)
                        acc[r][k] += __shfl_xor_sync(0xffffffffu, acc[r][k], o);
            #pragma unroll
            for (int r = 0; r < 4; r++) {
                float au[Kk], rsum = 0.f;
                #pragma unroll
                for (int k = 0; k < Kk; k++) {
                    au[k] = mixs[k] * (c1s[k] + acc[r][k]);
                    rsum += au[k];
                }
                float inv = 1.f / rsum;
                if (lane < Kk) {
                    float a = au[lane] * inv;
                    int lr = warp * 16 + g * 4 + r;
                    satt[lr][lane] = a;
                    if (it == NITER - 1)
                        g_attn[((size_t)b * Nn + rb + lr) * Kk + lane] = a;
                    cs += a;
                }
            }
        }
        if (lane < Kk) wcs[warp][lane] = cs;
        __syncthreads();
        if (t < Kk) {
            float S = 0.f;
            #pragma unroll
            for (int w = 0; w < 8; w++) S += wcs[w][t];   // fixed order
            g_Spart[((size_t)b * NCHB + y) * Kk + t] = S;
        }

        // ---- Phase B: mu / v2 partials over this block's 128 rows ----
        {
            int d0 = t * 2;
            float mu_[Kk][2], v2_[Kk][2];
            #pragma unroll
            for (int k = 0; k < Kk; k++) { mu_[k][0]=0.f; mu_[k][1]=0.f; v2_[k][0]=0.f; v2_[k][1]=0.f; }
            const float* vb = g_values + ((size_t)b * Nn + rb) * Dd + d0;
            for (int i = 0; i < 128; i++) {
                float2 v = *(const float2*)(vb + (size_t)i * Dd);
                float vx2 = v.x * v.x, vy2 = v.y * v.y;
                #pragma unroll
                for (int k = 0; k < Kk; k++) {
                    float a = satt[i][k];
                    mu_[k][0] += a * v.x;  mu_[k][1] += a * v.y;
                    v2_[k][0] += a * vx2;  v2_[k][1] += a * vy2;
                }
            }
            #pragma unroll
            for (int k = 0; k < Kk; k++) {
                size_t idx = (((size_t)y * Bb + b) * Kk + k) * Dd + d0;
                *(float2*)(g_mupart + idx) = make_float2(mu_[k][0], mu_[k][1]);
                *(float2*)(g_v2part + idx) = make_float2(v2_[k][0], v2_[k][1]);
            }
        }

        gbar();   // all partials visible chip-wide

        // ---- Reduce phase: this block reduces slot (b, k=y) ----
        {
            int k = y;
            float S = 0.f;
            #pragma unroll
            for (int c = 0; c < NCHB; c++)
                S += g_Spart[((size_t)b * NCHB + c) * Kk + k];   // fixed order
            float denom = S + c_EPS;
            float s = S / denom;
            float slog = 0.f, sqwq = 0.f;
            for (int d = t; d < Dd; d += 256) {
                float m = 0.f, v2 = 0.f;
                #pragma unroll
                for (int c = 0; c < NCHB; c++) {
                    size_t idx = (((size_t)c * Bb + b) * Kk + k) * Dd + d;
                    m  += g_mupart[idx];
                    v2 += g_v2part[idx];
                }
                m  /= denom;
                v2 /= denom;
                float sg = v2 - m * m * (2.f - s);
                if (it == NITER - 1) {
                    float sa = fmaxf(fabsf(sg), c_EPS);
                    out[(size_t)bk_ * Dd + d] = m + sa * noise_final[(size_t)bk_ * Dd + d];
                } else {
                    float w = 1.f / (sg * sg + c_EPS);
                    float q = g_q[(size_t)bk_ * Dd + d];
                    g_wq[(size_t)bk_ * Dd + d] = make_float2(w, q * w);
                    slog += logf(fabsf(sg) + c_EPS);
                    sqwq += q * q * w;
                }
            }
            if (it == NITER - 1) {
                // transposed attn out for (b, k): read all batch-b attn (written pre-barrier)
                float* ao = out + Bb * Kk * Dd + ((size_t)b * Kk + k) * Nn;
                float inv = 1.f / denom;
                for (int n = t; n < Nn; n += 256)
                    ao[n] = g_attn[((size_t)b * Nn + n) * Kk + k] * inv;
            } else {
                #pragma unroll
                for (int o = 16; o; o >>= 1) {
                    slog += __shfl_xor_sync(0xffffffffu, slog, o);
                    sqwq += __shfl_xor_sync(0xffffffffu, sqwq, o);
                }
                if ((t & 31) == 0) { sh[0][t >> 5] = slog; sh[1][t >> 5] = sqwq; }
                __syncthreads();
                if (t == 0) {
                    float SL = 0.f, SQ = 0.f;
                    #pragma unroll
                    for (int w = 0; w < 8; w++) { SL += sh[0][w]; SQ += sh[1][w]; }
                    g_c1[bk_] = -0.5f * (float)Dd * c_LOG2PI - 0.5f * SL - 0.5f * SQ;
                    g_mixing[bk_] = s / (float)Nn;
                }
            }
        }

        if (it < NITER - 1) gbar();   // wq/c1/mixing visible before next Phase A
    }
}

// ---------------- launcher ---------------------------------------------------
extern "C" void kernel_launch(void* const* d_in, const int* in_sizes, int n_in,
                              void* d_out, int out_size) {
    const float* embeddings = (const float*)d_in[0];
    const float* noise_init = (const float*)d_in[1];
    const float* noise_final= (const float*)d_in[2];
    const float* slots_mu   = (const float*)d_in[3];
    const float* slots_ls   = (const float*)d_in[4];
    const float* mixing     = (const float*)d_in[5];
    const float* Wk = (const float*)d_in[6];
    const float* bk = (const float*)d_in[7];
    const float* Wq = (const float*)d_in[8];
    const float* bq = (const float*)d_in[9];
    const float* Wv = (const float*)d_in[10];
    const float* bv = (const float*)d_in[11];
    const float* lng = (const float*)d_in[12];
    const float* lnb = (const float*)d_in[13];
    float* out = (float*)d_out;

    cudaFuncSetAttribute(mma_kv, cudaFuncAttributeMaxDynamicSharedMemorySize, MMA_SMEM);

    ln_split<<<Mtot, 128>>>(embeddings, lng, lnb);
    wt_split<<<dim3(32, 16), dim3(32, 8)>>>(Wk, Wv);
    init_slots_queries<<<Bb * Kk, 128>>>(noise_init, slots_mu, slots_ls, mixing, Wq, bq);
    mma_kv<<<dim3(Ntot / 128, Mtot / 128), 256, MMA_SMEM>>>(bk, bv);

    em_persist<<<dim3(Bb, NCHB), 256>>>(noise_final, out);
}

// round 15
// speedup vs baseline: 1.1213x; 1.1213x over previous
#include <cuda_runtime.h>
#include <cuda_fp16.h>
#include <cstdint>
#include <stdint.h>
#include <math.h>

#define Bb 16
#define Nn 1024
#define Dd 512
#define Kk 8
#define NITER 3
#define NCHB 8           // row-chunks per batch in persistent kernel (128 rows each)

#define Mtot (Bb*Nn)     // 16384
#define Ntot (2*Dd)      // 1024
#define LDA 40           // smem row stride (fp16): 32 + 8 pad, conflict-free ldmatrix
#define TILE_B (128*LDA*2)    // 10240 bytes
#define MMA_SMEM (2*3*TILE_B) // 2 stages x 3 tiles (Ahi, Alo, B) = 61440
#define NBLK (Bb*NCHB)   // 128 persistent blocks (<=148 SMs -> all wave-1 resident)

__device__ __constant__ float c_EPS = 1e-8f;
__device__ __constant__ float c_LNEPS = 1e-5f;
__device__ __constant__ float c_LOG2PI = 1.8378770664093453f;

// ---------------- scratch ----------------------------------------------------
__device__ float g_keys[Mtot*Dd];
__device__ float g_values[Mtot*Dd];
__device__ float g_q[Bb*Kk*Dd];
__device__ float g_sigma[Bb*Kk*Dd];
__device__ float2 g_wq[Bb*Kk*Dd];          // interleaved {w, q*w}
__device__ float g_c1[Bb*Kk];
__device__ float g_mixing[Bb*Kk];
__device__ float g_attn[Bb*Nn*Kk];
__device__ float g_Spart[Bb*NCHB*Kk];
__device__ float g_mupart[NCHB*Bb*Kk*Dd];
__device__ float g_v2part[NCHB*Bb*Kk*Dd];

__device__ __align__(16) __half g_Ahi[Mtot*Dd];
__device__ __align__(16) __half g_Alo[Mtot*Dd];
__device__ __align__(16) __half g_Bt[Ntot*Dd];    // W^T rows [n][k], single fp16

// global barrier state (sense-reversing; gen monotonically increases)
__device__ unsigned g_count = 0;
__device__ volatile unsigned g_gen = 0;

__device__ __forceinline__ void gbar() {
    __syncthreads();
    if (threadIdx.x == 0) {
        __threadfence();
        unsigned g = g_gen;
        if (atomicAdd(&g_count, 1u) == NBLK - 1u) {
            g_count = 0;
            __threadfence();
            g_gen = g + 1u;
        } else {
            while (g_gen == g) { }
            __threadfence();
        }
    }
    __syncthreads();
}

// ---------------- PTX helpers ------------------------------------------------
__device__ __forceinline__ uint32_t smem_u32(const void* p) {
    uint32_t a;
    asm("{ .reg .u64 t; cvta.to.shared.u64 t, %1; cvt.u32.u64 %0, t; }" : "=r"(a) : "l"(p));
    return a;
}
__device__ __forceinline__ void cpasync16(uint32_t saddr, const void* g) {
    asm volatile("cp.async.ca.shared.global [%0], [%1], 16;" :: "r"(saddr), "l"(g));
}
__device__ __forceinline__ void ldm4(uint32_t* r, uint32_t addr) {
    asm volatile("ldmatrix.sync.aligned.m8n8.x4.shared.b16 {%0,%1,%2,%3}, [%4];"
        : "=r"(r[0]), "=r"(r[1]), "=r"(r[2]), "=r"(r[3]) : "r"(addr));
}
__device__ __forceinline__ void mma16816(float* c, const uint32_t* a, const uint32_t* b) {
    asm volatile(
        "mma.sync.aligned.m16n8k16.row.col.f32.f16.f16.f32 "
        "{%0,%1,%2,%3}, {%4,%5,%6,%7}, {%8,%9}, {%0,%1,%2,%3};"
        : "+f"(c[0]), "+f"(c[1]), "+f"(c[2]), "+f"(c[3])
        : "r"(a[0]), "r"(a[1]), "r"(a[2]), "r"(a[3]), "r"(b[0]), "r"(b[1]));
}

// ---------------- K0: LN stats + fp16 hi/lo split ----------------------------
__global__ __launch_bounds__(128) void ln_split(
    const float* __restrict__ E, const float* __restrict__ lng, const float* __restrict__ lnb)
{
    int row = blockIdx.x;
    int t = threadIdx.x;
    float4 v = ((const float4*)(E + (size_t)row * Dd))[t];
    float s = v.x + v.y + v.z + v.w;
    float s2 = v.x*v.x + v.y*v.y + v.z*v.z + v.w*v.w;
    #pragma unroll
    for (int o = 16; o; o >>= 1) {
        s  += __shfl_xor_sync(0xffffffffu, s,  o);
        s2 += __shfl_xor_sync(0xffffffffu, s2, o);
    }
    __shared__ float sh[2][4];
    if ((t & 31) == 0) { sh[0][t >> 5] = s; sh[1][t >> 5] = s2; }
    __syncthreads();
    float S  = sh[0][0] + sh[0][1] + sh[0][2] + sh[0][3];
    float S2 = sh[1][0] + sh[1][1] + sh[1][2] + sh[1][3];
    float m = S / (float)Dd;
    float var = S2 / (float)Dd - m * m;
    float rs = rsqrtf(var + c_LNEPS);

    float4 g4 = ((const float4*)lng)[t];
    float4 b4 = ((const float4*)lnb)[t];
    float y[4];
    y[0] = (v.x - m) * rs * g4.x + b4.x;
    y[1] = (v.y - m) * rs * g4.y + b4.y;
    y[2] = (v.z - m) * rs * g4.z + b4.z;
    y[3] = (v.w - m) * rs * g4.w + b4.w;
    __half hi[4], lo[4];
    #pragma unroll
    for (int i = 0; i < 4; i++) {
        hi[i] = __float2half(y[i]);
        lo[i] = __float2half(y[i] - __half2float(hi[i]));
    }
    *(uint2*)(g_Ahi + (size_t)row * Dd + t * 4) = *(uint2*)hi;
    *(uint2*)(g_Alo + (size_t)row * Dd + t * 4) = *(uint2*)lo;
}

// ---------------- K1: W^T fp16 (Bt[n][k] = W[k][n]) --------------------------
__global__ void wt_split(const float* __restrict__ Wk, const float* __restrict__ Wv) {
    __shared__ float tile[32][33];
    int n0 = blockIdx.x * 32;
    int k0 = blockIdx.y * 32;
    const float* W = (n0 < Dd) ? Wk : Wv;
    int nc0 = n0 & (Dd - 1);
    int tx = threadIdx.x, ty = threadIdx.y;
    #pragma unroll
    for (int i = ty; i < 32; i += 8)
        tile[i][tx] = W[(size_t)(k0 + i) * Dd + nc0 + tx];
    __syncthreads();
    #pragma unroll
    for (int i = ty; i < 32; i += 8)
        g_Bt[(size_t)(n0 + i) * Dd + k0 + tx] = __float2half(tile[tx][i]);
}

// ---------------- K2: HMMA fp16x2 GEMM -> keys|values ------------------------
// C = (Ahi + Alo) @ Bt^T, both products accumulate into the same fp32 acc.
__global__ __launch_bounds__(256, 2) void mma_kv(
    const float* __restrict__ bk, const float* __restrict__ bv)
{
    extern __shared__ char dsm[];
    int tid = threadIdx.x, lane = tid & 31, wid = tid >> 5;
    int warp_m = wid >> 1, warp_n = wid & 1;
    int n0 = blockIdx.x * 128;
    int m0 = blockIdx.y * 128;

    float acc[2][8][4];
    #pragma unroll
    for (int i = 0; i < 2; i++)
        #pragma unroll
        for (int j = 0; j < 8; j++)
            #pragma unroll
            for (int q = 0; q < 4; q++) acc[i][j][q] = 0.f;

    const int lrow = tid >> 1;
    const int lseg = (tid & 1) * 2;

    #pragma unroll
    for (int j = 0; j < 2; j++) {
        int off = (lseg + j) * 8;
        size_t ao = (size_t)(m0 + lrow) * Dd + off;
        size_t bo = (size_t)(n0 + lrow) * Dd + off;
        uint32_t so = lrow * LDA * 2 + off * 2;
        cpasync16(smem_u32(dsm + 0*TILE_B + so), g_Ahi + ao);
        cpasync16(smem_u32(dsm + 1*TILE_B + so), g_Alo + ao);
        cpasync16(smem_u32(dsm + 2*TILE_B + so), g_Bt + bo);
    }
    asm volatile("cp.async.commit_group;" ::: "memory");

    for (int kc = 0; kc < 16; kc++) {
        int buf = kc & 1;
        char* cur = dsm + buf * 3 * TILE_B;
        if (kc < 15) {
            char* nxt = dsm + (buf ^ 1) * 3 * TILE_B;
            int kn = (kc + 1) * 32;
            #pragma unroll
            for (int j = 0; j < 2; j++) {
                int off = (lseg + j) * 8;
                size_t ao = (size_t)(m0 + lrow) * Dd + kn + off;
                size_t bo = (size_t)(n0 + lrow) * Dd + kn + off;
                uint32_t so = lrow * LDA * 2 + off * 2;
                cpasync16(smem_u32(nxt + 0*TILE_B + so), g_Ahi + ao);
                cpasync16(smem_u32(nxt + 1*TILE_B + so), g_Alo + ao);
                cpasync16(smem_u32(nxt + 2*TILE_B + so), g_Bt + bo);
            }
            asm volatile("cp.async.commit_group;" ::: "memory");
            asm volatile("cp.async.wait_group 1;" ::: "memory");
        } else {
            asm volatile("cp.async.wait_group 0;" ::: "memory");
        }
        __syncthreads();

        const __half* sAhi = (const __half*)(cur + 0*TILE_B);
        const __half* sAlo = (const __half*)(cur + 1*TILE_B);
        const __half* sB   = (const __half*)(cur + 2*TILE_B);

        #pragma unroll
        for (int ks = 0; ks < 2; ks++) {
            uint32_t ahi[2][4], alo[2][4];
            #pragma unroll
            for (int mi = 0; mi < 2; mi++) {
                int row = warp_m * 32 + mi * 16 + (lane & 15);
                int col = ks * 16 + (lane >> 4) * 8;
                ldm4(ahi[mi], smem_u32(&sAhi[row * LDA + col]));
                ldm4(alo[mi], smem_u32(&sAlo[row * LDA + col]));
            }
            #pragma unroll
            for (int h = 0; h < 2; h++) {
                uint32_t bb[4][2];
                #pragma unroll
                for (int jj = 0; jj < 2; jj++) {
                    int nrow = warp_n * 64 + h * 32 + jj * 16 + (lane & 7) + ((lane >> 4) << 3);
                    int col = ks * 16 + ((lane >> 3) & 1) * 8;
                    uint32_t r4[4];
                    ldm4(r4, smem_u32(&sB[nrow * LDA + col]));
                    bb[2*jj][0] = r4[0]; bb[2*jj][1] = r4[1];
                    bb[2*jj+1][0] = r4[2]; bb[2*jj+1][1] = r4[3];
                }
                #pragma unroll
                for (int mi = 0; mi < 2; mi++)
                    #pragma unroll
                    for (int j2 = 0; j2 < 4; j2++) {
                        int nj = h * 4 + j2;
                        mma16816(acc[mi][nj], ahi[mi], bb[j2]);
                        mma16816(acc[mi][nj], alo[mi], bb[j2]);
                    }
            }
        }
        __syncthreads();
    }

    const bool isK = (n0 < Dd);
    float* Dst = isK ? g_keys : g_values;
    const float* bias = isK ? bk : bv;
    int nbase = (isK ? n0 : n0 - Dd) + warp_n * 64;
    int mbase = m0 + warp_m * 32;
    int r = lane >> 2, cp = 2 * (lane & 3);
    #pragma unroll
    for (int mi = 0; mi < 2; mi++) {
        #pragma unroll
        for (int nj = 0; nj < 8; nj++) {
            int n = nbase + nj * 8 + cp;
            float b0 = bias[n], b1 = bias[n + 1];
            int m = mbase + mi * 16 + r;
            float2 o0 = { acc[mi][nj][0] + b0, acc[mi][nj][1] + b1 };
            float2 o1 = { acc[mi][nj][2] + b0, acc[mi][nj][3] + b1 };
            *(float2*)&Dst[(size_t)m * Dd + n] = o0;
            *(float2*)&Dst[(size_t)(m + 8) * Dd + n] = o1;
        }
    }
}

// ---------------- K3: slots, queries, AND iter-0 prep (w/qw/c1) --------------
__global__ void init_slots_queries(
    const float* __restrict__ noise_init, const float* __restrict__ slots_mu,
    const float* __restrict__ slots_ls,   const float* __restrict__ mix_in,
    const float* __restrict__ Wq,         const float* __restrict__ bq)
{
    int bk_ = blockIdx.x;
    int b = bk_ >> 3, k = bk_ & 7;
    __shared__ float slot[Dd];
    int t = threadIdx.x;
    for (int d = t; d < Dd; d += 128) {
        float sg = expf(slots_ls[k * Dd + d]);
        slot[d] = slots_mu[k * Dd + d] + sg * noise_init[((size_t)b * Kk + k) * Dd + d];
        g_sigma[((size_t)b * Kk + k) * Dd + d] = sg;
    }
    if (t == 0) g_mixing[b * Kk + k] = mix_in[k];
    __syncthreads();
    float slog = 0.f, sqwq = 0.f;
    for (int j = t; j < Dd; j += 128) {
        float acc = bq[j];
        for (int d = 0; d < Dd; d++) acc += slot[d] * Wq[(size_t)d * Dd + j];
        g_q[((size_t)bk_) * Dd + j] = acc;
        float sg = g_sigma[(size_t)bk_ * Dd + j];
        float w = 1.f / (sg * sg + c_EPS);
        g_wq[(size_t)bk_ * Dd + j] = make_float2(w, acc * w);
        slog += logf(fabsf(sg) + c_EPS);
        sqwq += acc * acc * w;
    }
    #pragma unroll
    for (int o = 16; o; o >>= 1) {
        slog += __shfl_xor_sync(0xffffffffu, slog, o);
        sqwq += __shfl_xor_sync(0xffffffffu, sqwq, o);
    }
    __shared__ float sh[2][4];
    if ((t & 31) == 0) { sh[0][t >> 5] = slog; sh[1][t >> 5] = sqwq; }
    __syncthreads();
    if (t == 0) {
        float SL = sh[0][0] + sh[0][1] + sh[0][2] + sh[0][3];
        float SQ = sh[1][0] + sh[1][1] + sh[1][2] + sh[1][3];
        g_c1[bk_] = -0.5f * (float)Dd * c_LOG2PI - 0.5f * SL - 0.5f * SQ;
    }
}

// ---------------- K4: persistent EM loop (all 3 iterations, 1 launch) --------
__global__ __launch_bounds__(256) void em_persist(
    const float* __restrict__ noise_final, float* __restrict__ out)
{
    int b = blockIdx.x, y = blockIdx.y;
    int t = threadIdx.x, warp = t >> 5, lane = t & 31;
    __shared__ float2 swq[Kk * Dd];          // 32KB
    __shared__ float satt[128][Kk];          // 4KB
    __shared__ float wcs[8][Kk];
    __shared__ float c1s[Kk], mixs[Kk];
    __shared__ float sh[2][8];

    const int rb = y * 128;
    const int bk_ = b * Kk + y;

    for (int it = 0; it < NITER; it++) {
        for (int i = t; i < Kk * Dd; i += 256)
            swq[i] = g_wq[(size_t)b * Kk * Dd + i];
        if (t < Kk) { c1s[t] = g_c1[b * Kk + t]; mixs[t] = g_mixing[b * Kk + t]; }
        __syncthreads();

        // Phase A: attn for 128 rows; warp owns 16 rows (4 groups of 4)
        float cs = 0.f;
        for (int g = 0; g < 4; g++) {
            int r0 = rb + warp * 16 + g * 4;
            const float* kb = g_keys + ((size_t)b * Nn + r0) * Dd;
            float acc[4][Kk];
            #pragma unroll
            for (int r = 0; r < 4; r++)
                #pragma unroll
                for (int k = 0; k < Kk; k++) acc[r][k] = 0.f;
            #pragma unroll
            for (int i = 0; i < 16; i++) {
                int d = lane + 32 * i;
                float kv0 = kb[d], kv1 = kb[Dd + d], kv2 = kb[2*Dd + d], kv3 = kb[3*Dd + d];
                float h0 = -0.5f*kv0*kv0, h1 = -0.5f*kv1*kv1, h2 = -0.5f*kv2*kv2, h3 = -0.5f*kv3*kv3;
                #pragma unroll
                for (int k = 0; k < Kk; k++) {
                    float2 wq = swq[k * Dd + d];
                    acc[0][k] = fmaf(kv0, wq.y, fmaf(h0, wq.x, acc[0][k]));
                    acc[1][k] = fmaf(kv1, wq.y, fmaf(h1, wq.x, acc[1][k]));
                    acc[2][k] = fmaf(kv2, wq.y, fmaf(h2, wq.x, acc[2][k]));
                    acc[3][k] = fmaf(kv3, wq.y, fmaf(h3, wq.x, acc[3][k]));
                }
            }
            #pragma unroll
            for (int o = 16; o; o >>= 1)
                #pragma unroll
                for (int r = 0; r < 4; r++)
                    #pragma unroll
                    for (int k = 0; k < Kk; k++)
                        acc[r][k] += __shfl_xor_sync(0xffffffffu, acc[r][k], o);
            #pragma unroll
            for (int r = 0; r < 4; r++) {
                float au[Kk], rsum = 0.f;
                #pragma unroll
                for (int k = 0; k < Kk; k++) {
                    au[k] = mixs[k] * (c1s[k] + acc[r][k]);
                    rsum += au[k];
                }
                float inv = 1.f / rsum;
                if (lane < Kk) {
                    float a = au[lane] * inv;
                    int lr = warp * 16 + g * 4 + r;
                    satt[lr][lane] = a;
                    if (it == NITER - 1)
                        g_attn[((size_t)b * Nn + rb + lr) * Kk + lane] = a;
                    cs += a;
                }
            }
        }
        if (lane < Kk) wcs[warp][lane] = cs;
        __syncthreads();
        if (t < Kk) {
            float S = 0.f;
            #pragma unroll
            for (int w = 0; w < 8; w++) S += wcs[w][t];   // fixed order
            g_Spart[((size_t)b * NCHB + y) * Kk + t] = S;
        }

        // Phase B: mu / v2 partials over this block's 128 rows
        {
            int d0 = t * 2;
            float mu_[Kk][2], v2_[Kk][2];
            #pragma unroll
            for (int k = 0; k < Kk; k++) { mu_[k][0]=0.f; mu_[k][1]=0.f; v2_[k][0]=0.f; v2_[k][1]=0.f; }
            const float* vb = g_values + ((size_t)b * Nn + rb) * Dd + d0;
            for (int i = 0; i < 128; i++) {
                float2 v = *(const float2*)(vb + (size_t)i * Dd);
                float vx2 = v.x * v.x, vy2 = v.y * v.y;
                #pragma unroll
                for (int k = 0; k < Kk; k++) {
                    float a = satt[i][k];
                    mu_[k][0] += a * v.x;  mu_[k][1] += a * v.y;
                    v2_[k][0] += a * vx2;  v2_[k][1] += a * vy2;
                }
            }
            #pragma unroll
            for (int k = 0; k < Kk; k++) {
                size_t idx = (((size_t)y * Bb + b) * Kk + k) * Dd + d0;
                *(float2*)(g_mupart + idx) = make_float2(mu_[k][0], mu_[k][1]);
                *(float2*)(g_v2part + idx) = make_float2(v2_[k][0], v2_[k][1]);
            }
        }

        gbar();

        // Reduce phase: this block reduces slot (b, k=y)
        {
            int k = y;
            float S = 0.f;
            #pragma unroll
            for (int c = 0; c < NCHB; c++)
                S += g_Spart[((size_t)b * NCHB + c) * Kk + k];   // fixed order
            float denom = S + c_EPS;
            float s = S / denom;
            float slog = 0.f, sqwq = 0.f;
            for (int d = t; d < Dd; d += 256) {
                float m = 0.f, v2 = 0.f;
                #pragma unroll
                for (int c = 0; c < NCHB; c++) {
                    size_t idx = (((size_t)c * Bb + b) * Kk + k) * Dd + d;
                    m  += g_mupart[idx];
                    v2 += g_v2part[idx];
                }
                m  /= denom;
                v2 /= denom;
                float sg = v2 - m * m * (2.f - s);
                if (it == NITER - 1) {
                    float sa = fmaxf(fabsf(sg), c_EPS);
                    out[(size_t)bk_ * Dd + d] = m + sa * noise_final[(size_t)bk_ * Dd + d];
                } else {
                    float w = 1.f / (sg * sg + c_EPS);
                    float q = g_q[(size_t)bk_ * Dd + d];
                    g_wq[(size_t)bk_ * Dd + d] = make_float2(w, q * w);
                    slog += logf(fabsf(sg) + c_EPS);
                    sqwq += q * q * w;
                }
            }
            if (it == NITER - 1) {
                float* ao = out + Bb * Kk * Dd + ((size_t)b * Kk + k) * Nn;
                float inv = 1.f / denom;
                for (int n = t; n < Nn; n += 256)
                    ao[n] = g_attn[((size_t)b * Nn + n) * Kk + k] * inv;
            } else {
                #pragma unroll
                for (int o = 16; o; o >>= 1) {
                    slog += __shfl_xor_sync(0xffffffffu, slog, o);
                    sqwq += __shfl_xor_sync(0xffffffffu, sqwq, o);
                }
                if ((t & 31) == 0) { sh[0][t >> 5] = slog; sh[1][t >> 5] = sqwq; }
                __syncthreads();
                if (t == 0) {
                    float SL = 0.f, SQ = 0.f;
                    #pragma unroll
                    for (int w = 0; w < 8; w++) { SL += sh[0][w]; SQ += sh[1][w]; }
                    g_c1[bk_] = -0.5f * (float)Dd * c_LOG2PI - 0.5f * SL - 0.5f * SQ;
                    g_mixing[bk_] = s / (float)Nn;
                }
            }
        }

        if (it < NITER - 1) gbar();
    }
}

// ---------------- launcher ---------------------------------------------------
extern "C" void kernel_launch(void* const* d_in, const int* in_sizes, int n_in,
                              void* d_out, int out_size) {
    const float* embeddings = (const float*)d_in[0];
    const float* noise_init = (const float*)d_in[1];
    const float* noise_final= (const float*)d_in[2];
    const float* slots_mu   = (const float*)d_in[3];
    const float* slots_ls   = (const float*)d_in[4];
    const float* mixing     = (const float*)d_in[5];
    const float* Wk = (const float*)d_in[6];
    const float* bk = (const float*)d_in[7];
    const float* Wq = (const float*)d_in[8];
    const float* bq = (const float*)d_in[9];
    const float* Wv = (const float*)d_in[10];
    const float* bv = (const float*)d_in[11];
    const float* lng = (const float*)d_in[12];
    const float* lnb = (const float*)d_in[13];
    float* out = (float*)d_out;

    cudaFuncSetAttribute(mma_kv, cudaFuncAttributeMaxDynamicSharedMemorySize, MMA_SMEM);

    ln_split<<<Mtot, 128>>>(embeddings, lng, lnb);
    wt_split<<<dim3(32, 16), dim3(32, 8)>>>(Wk, Wv);
    init_slots_queries<<<Bb * Kk, 128>>>(noise_init, slots_mu, slots_ls, mixing, Wq, bq);
    mma_kv<<<dim3(Ntot / 128, Mtot / 128), 256, MMA_SMEM>>>(bk, bv);

    em_persist<<<dim3(Bb, NCHB), 256>>>(noise_final, out);
}

// round 16
// speedup vs baseline: 1.3448x; 1.1994x over previous
#include <cuda_runtime.h>
#include <cuda_fp16.h>
#include <cstdint>
#include <stdint.h>
#include <math.h>

#define Bb 16
#define Nn 1024
#define Dd 512
#define Kk 8
#define NITER 3
#define NCHB 8           // row-chunks per batch in persistent kernel (128 rows each)

#define Mtot (Bb*Nn)     // 16384
#define Ntot (2*Dd)      // 1024
#define LDA 40           // smem row stride (fp16): 32 + 8 pad, conflict-free ldmatrix
#define TILE_B (128*LDA*2)    // 10240 bytes
#define MMA_SMEM (2*3*TILE_B) // 61440
#define NBLK (Bb*NCHB)   // 128 persistent blocks (<=148 SMs -> all wave-1 resident)
#define EMT 512          // em_persist threads (16 warps)

__device__ __constant__ float c_EPS = 1e-8f;
__device__ __constant__ float c_LNEPS = 1e-5f;
__device__ __constant__ float c_LOG2PI = 1.8378770664093453f;

// ---------------- scratch ----------------------------------------------------
__device__ float g_keys[Mtot*Dd];
__device__ float g_values[Mtot*Dd];
__device__ float g_q[Bb*Kk*Dd];
__device__ float g_sigma[Bb*Kk*Dd];
__device__ float2 g_wq[Bb*Kk*Dd];          // interleaved {w, q*w}
__device__ float g_c1[Bb*Kk];
__device__ float g_mixing[Bb*Kk];
__device__ float g_attn[Bb*Nn*Kk];
__device__ float g_Spart[Bb*NCHB*Kk];
__device__ float g_mupart[NCHB*Bb*Kk*Dd];
__device__ float g_v2part[NCHB*Bb*Kk*Dd];

__device__ __align__(16) __half g_Ahi[Mtot*Dd];
__device__ __align__(16) __half g_Alo[Mtot*Dd];
__device__ __align__(16) __half g_Bt[Ntot*Dd];    // W^T rows [n][k], single fp16

// global barrier state (sense-reversing)
__device__ unsigned g_count = 0;
__device__ volatile unsigned g_gen = 0;

__device__ __forceinline__ void gbar() {
    __syncthreads();
    if (threadIdx.x == 0) {
        __threadfence();
        unsigned g = g_gen;
        if (atomicAdd(&g_count, 1u) == NBLK - 1u) {
            g_count = 0;
            __threadfence();
            g_gen = g + 1u;
        } else {
            while (g_gen == g) { }
            __threadfence();
        }
    }
    __syncthreads();
}

// ---------------- PTX helpers ------------------------------------------------
__device__ __forceinline__ uint32_t smem_u32(const void* p) {
    uint32_t a;
    asm("{ .reg .u64 t; cvta.to.shared.u64 t, %1; cvt.u32.u64 %0, t; }" : "=r"(a) : "l"(p));
    return a;
}
__device__ __forceinline__ void cpasync16(uint32_t saddr, const void* g) {
    asm volatile("cp.async.ca.shared.global [%0], [%1], 16;" :: "r"(saddr), "l"(g));
}
__device__ __forceinline__ void ldm4(uint32_t* r, uint32_t addr) {
    asm volatile("ldmatrix.sync.aligned.m8n8.x4.shared.b16 {%0,%1,%2,%3}, [%4];"
        : "=r"(r[0]), "=r"(r[1]), "=r"(r[2]), "=r"(r[3]) : "r"(addr));
}
__device__ __forceinline__ void mma16816(float* c, const uint32_t* a, const uint32_t* b) {
    asm volatile(
        "mma.sync.aligned.m16n8k16.row.col.f32.f16.f16.f32 "
        "{%0,%1,%2,%3}, {%4,%5,%6,%7}, {%8,%9}, {%0,%1,%2,%3};"
        : "+f"(c[0]), "+f"(c[1]), "+f"(c[2]), "+f"(c[3])
        : "r"(a[0]), "r"(a[1]), "r"(a[2]), "r"(a[3]), "r"(b[0]), "r"(b[1]));
}

// ---------------- K0: LN stats + fp16 hi/lo split ----------------------------
__global__ __launch_bounds__(128) void ln_split(
    const float* __restrict__ E, const float* __restrict__ lng, const float* __restrict__ lnb)
{
    int row = blockIdx.x;
    int t = threadIdx.x;
    float4 v = ((const float4*)(E + (size_t)row * Dd))[t];
    float s = v.x + v.y + v.z + v.w;
    float s2 = v.x*v.x + v.y*v.y + v.z*v.z + v.w*v.w;
    #pragma unroll
    for (int o = 16; o; o >>= 1) {
        s  += __shfl_xor_sync(0xffffffffu, s,  o);
        s2 += __shfl_xor_sync(0xffffffffu, s2, o);
    }
    __shared__ float sh[2][4];
    if ((t & 31) == 0) { sh[0][t >> 5] = s; sh[1][t >> 5] = s2; }
    __syncthreads();
    float S  = sh[0][0] + sh[0][1] + sh[0][2] + sh[0][3];
    float S2 = sh[1][0] + sh[1][1] + sh[1][2] + sh[1][3];
    float m = S / (float)Dd;
    float var = S2 / (float)Dd - m * m;
    float rs = rsqrtf(var + c_LNEPS);

    float4 g4 = ((const float4*)lng)[t];
    float4 b4 = ((const float4*)lnb)[t];
    float y[4];
    y[0] = (v.x - m) * rs * g4.x + b4.x;
    y[1] = (v.y - m) * rs * g4.y + b4.y;
    y[2] = (v.z - m) * rs * g4.z + b4.z;
    y[3] = (v.w - m) * rs * g4.w + b4.w;
    __half hi[4], lo[4];
    #pragma unroll
    for (int i = 0; i < 4; i++) {
        hi[i] = __float2half(y[i]);
        lo[i] = __float2half(y[i] - __half2float(hi[i]));
    }
    *(uint2*)(g_Ahi + (size_t)row * Dd + t * 4) = *(uint2*)hi;
    *(uint2*)(g_Alo + (size_t)row * Dd + t * 4) = *(uint2*)lo;
}

// ---------------- K1: W^T fp16 (Bt[n][k] = W[k][n]) --------------------------
__global__ void wt_split(const float* __restrict__ Wk, const float* __restrict__ Wv) {
    __shared__ float tile[32][33];
    int n0 = blockIdx.x * 32;
    int k0 = blockIdx.y * 32;
    const float* W = (n0 < Dd) ? Wk : Wv;
    int nc0 = n0 & (Dd - 1);
    int tx = threadIdx.x, ty = threadIdx.y;
    #pragma unroll
    for (int i = ty; i < 32; i += 8)
        tile[i][tx] = W[(size_t)(k0 + i) * Dd + nc0 + tx];
    __syncthreads();
    #pragma unroll
    for (int i = ty; i < 32; i += 8)
        g_Bt[(size_t)(n0 + i) * Dd + k0 + tx] = __float2half(tile[tx][i]);
}

// ---------------- K2: HMMA fp16x2 GEMM (unchanged; ~112us) -------------------
__global__ __launch_bounds__(256, 2) void mma_kv(
    const float* __restrict__ bk, const float* __restrict__ bv)
{
    extern __shared__ char dsm[];
    int tid = threadIdx.x, lane = tid & 31, wid = tid >> 5;
    int warp_m = wid >> 1, warp_n = wid & 1;
    int n0 = blockIdx.x * 128;
    int m0 = blockIdx.y * 128;

    float acc[2][8][4];
    #pragma unroll
    for (int i = 0; i < 2; i++)
        #pragma unroll
        for (int j = 0; j < 8; j++)
            #pragma unroll
            for (int q = 0; q < 4; q++) acc[i][j][q] = 0.f;

    const int lrow = tid >> 1;
    const int lseg = (tid & 1) * 2;

    #pragma unroll
    for (int j = 0; j < 2; j++) {
        int off = (lseg + j) * 8;
        size_t ao = (size_t)(m0 + lrow) * Dd + off;
        size_t bo = (size_t)(n0 + lrow) * Dd + off;
        uint32_t so = lrow * LDA * 2 + off * 2;
        cpasync16(smem_u32(dsm + 0*TILE_B + so), g_Ahi + ao);
        cpasync16(smem_u32(dsm + 1*TILE_B + so), g_Alo + ao);
        cpasync16(smem_u32(dsm + 2*TILE_B + so), g_Bt + bo);
    }
    asm volatile("cp.async.commit_group;" ::: "memory");

    for (int kc = 0; kc < 16; kc++) {
        int buf = kc & 1;
        char* cur = dsm + buf * 3 * TILE_B;
        if (kc < 15) {
            char* nxt = dsm + (buf ^ 1) * 3 * TILE_B;
            int kn = (kc + 1) * 32;
            #pragma unroll
            for (int j = 0; j < 2; j++) {
                int off = (lseg + j) * 8;
                size_t ao = (size_t)(m0 + lrow) * Dd + kn + off;
                size_t bo = (size_t)(n0 + lrow) * Dd + kn + off;
                uint32_t so = lrow * LDA * 2 + off * 2;
                cpasync16(smem_u32(nxt + 0*TILE_B + so), g_Ahi + ao);
                cpasync16(smem_u32(nxt + 1*TILE_B + so), g_Alo + ao);
                cpasync16(smem_u32(nxt + 2*TILE_B + so), g_Bt + bo);
            }
            asm volatile("cp.async.commit_group;" ::: "memory");
            asm volatile("cp.async.wait_group 1;" ::: "memory");
        } else {
            asm volatile("cp.async.wait_group 0;" ::: "memory");
        }
        __syncthreads();

        const __half* sAhi = (const __half*)(cur + 0*TILE_B);
        const __half* sAlo = (const __half*)(cur + 1*TILE_B);
        const __half* sB   = (const __half*)(cur + 2*TILE_B);

        #pragma unroll
        for (int ks = 0; ks < 2; ks++) {
            uint32_t ahi[2][4], alo[2][4];
            #pragma unroll
            for (int mi = 0; mi < 2; mi++) {
                int row = warp_m * 32 + mi * 16 + (lane & 15);
                int col = ks * 16 + (lane >> 4) * 8;
                ldm4(ahi[mi], smem_u32(&sAhi[row * LDA + col]));
                ldm4(alo[mi], smem_u32(&sAlo[row * LDA + col]));
            }
            #pragma unroll
            for (int h = 0; h < 2; h++) {
                uint32_t bb[4][2];
                #pragma unroll
                for (int jj = 0; jj < 2; jj++) {
                    int nrow = warp_n * 64 + h * 32 + jj * 16 + (lane & 7) + ((lane >> 4) << 3);
                    int col = ks * 16 + ((lane >> 3) & 1) * 8;
                    uint32_t r4[4];
                    ldm4(r4, smem_u32(&sB[nrow * LDA + col]));
                    bb[2*jj][0] = r4[0]; bb[2*jj][1] = r4[1];
                    bb[2*jj+1][0] = r4[2]; bb[2*jj+1][1] = r4[3];
                }
                #pragma unroll
                for (int mi = 0; mi < 2; mi++)
                    #pragma unroll
                    for (int j2 = 0; j2 < 4; j2++) {
                        int nj = h * 4 + j2;
                        mma16816(acc[mi][nj], ahi[mi], bb[j2]);
                        mma16816(acc[mi][nj], alo[mi], bb[j2]);
                    }
            }
        }
        __syncthreads();
    }

    const bool isK = (n0 < Dd);
    float* Dst = isK ? g_keys : g_values;
    const float* bias = isK ? bk : bv;
    int nbase = (isK ? n0 : n0 - Dd) + warp_n * 64;
    int mbase = m0 + warp_m * 32;
    int r = lane >> 2, cp = 2 * (lane & 3);
    #pragma unroll
    for (int mi = 0; mi < 2; mi++) {
        #pragma unroll
        for (int nj = 0; nj < 8; nj++) {
            int n = nbase + nj * 8 + cp;
            float b0 = bias[n], b1 = bias[n + 1];
            int m = mbase + mi * 16 + r;
            float2 o0 = { acc[mi][nj][0] + b0, acc[mi][nj][1] + b1 };
            float2 o1 = { acc[mi][nj][2] + b0, acc[mi][nj][3] + b1 };
            *(float2*)&Dst[(size_t)m * Dd + n] = o0;
            *(float2*)&Dst[(size_t)(m + 8) * Dd + n] = o1;
        }
    }
}

// ---------------- K3: slots, queries, AND iter-0 prep (w/qw/c1) --------------
__global__ void init_slots_queries(
    const float* __restrict__ noise_init, const float* __restrict__ slots_mu,
    const float* __restrict__ slots_ls,   const float* __restrict__ mix_in,
    const float* __restrict__ Wq,         const float* __restrict__ bq)
{
    int bk_ = blockIdx.x;
    int b = bk_ >> 3, k = bk_ & 7;
    __shared__ float slot[Dd];
    int t = threadIdx.x;
    for (int d = t; d < Dd; d += 128) {
        float sg = expf(slots_ls[k * Dd + d]);
        slot[d] = slots_mu[k * Dd + d] + sg * noise_init[((size_t)b * Kk + k) * Dd + d];
        g_sigma[((size_t)b * Kk + k) * Dd + d] = sg;
    }
    if (t == 0) g_mixing[b * Kk + k] = mix_in[k];
    __syncthreads();
    float slog = 0.f, sqwq = 0.f;
    for (int j = t; j < Dd; j += 128) {
        float acc = bq[j];
        for (int d = 0; d < Dd; d++) acc += slot[d] * Wq[(size_t)d * Dd + j];
        g_q[((size_t)bk_) * Dd + j] = acc;
        float sg = g_sigma[(size_t)bk_ * Dd + j];
        float w = 1.f / (sg * sg + c_EPS);
        g_wq[(size_t)bk_ * Dd + j] = make_float2(w, acc * w);
        slog += logf(fabsf(sg) + c_EPS);
        sqwq += acc * acc * w;
    }
    #pragma unroll
    for (int o = 16; o; o >>= 1) {
        slog += __shfl_xor_sync(0xffffffffu, slog, o);
        sqwq += __shfl_xor_sync(0xffffffffu, sqwq, o);
    }
    __shared__ float sh[2][4];
    if ((t & 31) == 0) { sh[0][t >> 5] = slog; sh[1][t >> 5] = sqwq; }
    __syncthreads();
    if (t == 0) {
        float SL = sh[0][0] + sh[0][1] + sh[0][2] + sh[0][3];
        float SQ = sh[1][0] + sh[1][1] + sh[1][2] + sh[1][3];
        g_c1[bk_] = -0.5f * (float)Dd * c_LOG2PI - 0.5f * SL - 0.5f * SQ;
    }
}

// ---------------- K4: persistent EM loop (512 threads, 8-row Phase A) --------
__global__ __launch_bounds__(EMT) void em_persist(
    const float* __restrict__ noise_final, float* __restrict__ out)
{
    int b = blockIdx.x, y = blockIdx.y;
    int t = threadIdx.x, warp = t >> 5, lane = t & 31;
    __shared__ float2 swq[Kk * Dd];                 // 32KB
    __shared__ __align__(16) float satt[128][Kk];   // 4KB, float4-readable
    __shared__ float wcs[16][Kk];
    __shared__ float c1s[Kk], mixs[Kk];
    __shared__ float sh[2][16];

    const int rb = y * 128;
    const int bk_ = b * Kk + y;

    for (int it = 0; it < NITER; it++) {
        for (int i = t; i < Kk * Dd; i += EMT)
            swq[i] = g_wq[(size_t)b * Kk * Dd + i];
        if (t < Kk) { c1s[t] = g_c1[b * Kk + t]; mixs[t] = g_mixing[b * Kk + t]; }
        __syncthreads();

        // ---- Phase A: warp owns 8 rows; one swq load serves all 8 ----
        {
            int r0 = rb + warp * 8;
            const float* kb = g_keys + ((size_t)b * Nn + r0) * Dd;
            float acc[8][Kk];
            #pragma unroll
            for (int r = 0; r < 8; r++)
                #pragma unroll
                for (int k = 0; k < Kk; k++) acc[r][k] = 0.f;

            #pragma unroll 4
            for (int i = 0; i < 16; i++) {
                int d = lane + 32 * i;
                float kv[8], hh[8];
                #pragma unroll
                for (int r = 0; r < 8; r++) {
                    kv[r] = kb[(size_t)r * Dd + d];
                    hh[r] = -0.5f * kv[r] * kv[r];
                }
                #pragma unroll
                for (int k = 0; k < Kk; k++) {
                    float2 wq = swq[k * Dd + d];
                    #pragma unroll
                    for (int r = 0; r < 8; r++)
                        acc[r][k] = fmaf(kv[r], wq.y, fmaf(hh[r], wq.x, acc[r][k]));
                }
            }
            #pragma unroll
            for (int o = 16; o; o >>= 1)
                #pragma unroll
                for (int r = 0; r < 8; r++)
                    #pragma unroll
                    for (int k = 0; k < Kk; k++)
                        acc[r][k] += __shfl_xor_sync(0xffffffffu, acc[r][k], o);

            float cs = 0.f;
            #pragma unroll
            for (int r = 0; r < 8; r++) {
                float au[Kk], rsum = 0.f;
                #pragma unroll
                for (int k = 0; k < Kk; k++) {
                    au[k] = mixs[k] * (c1s[k] + acc[r][k]);
                    rsum += au[k];
                }
                float inv = 1.f / rsum;
                if (lane < Kk) {
                    float a = au[lane] * inv;
                    int lr = warp * 8 + r;
                    satt[lr][lane] = a;
                    if (it == NITER - 1)
                        g_attn[((size_t)b * Nn + rb + lr) * Kk + lane] = a;
                    cs += a;
                }
            }
            if (lane < Kk) wcs[warp][lane] = cs;
        }
        __syncthreads();
        if (t < Kk) {
            float S = 0.f;
            #pragma unroll
            for (int w = 0; w < 16; w++) S += wcs[w][t];   // fixed order
            g_Spart[((size_t)b * NCHB + y) * Kk + t] = S;
        }

        // ---- Phase B: mu / v2 partials; thread owns 1 d (512 threads) ----
        {
            float mu_[Kk], v2_[Kk];
            #pragma unroll
            for (int k = 0; k < Kk; k++) { mu_[k] = 0.f; v2_[k] = 0.f; }
            const float* vb = g_values + ((size_t)b * Nn + rb) * Dd + t;
            #pragma unroll 4
            for (int i = 0; i < 128; i++) {
                float v = vb[(size_t)i * Dd];
                float vv = v * v;
                float4 a0 = *(const float4*)&satt[i][0];   // broadcast
                float4 a1 = *(const float4*)&satt[i][4];
                mu_[0] = fmaf(a0.x, v, mu_[0]);  v2_[0] = fmaf(a0.x, vv, v2_[0]);
                mu_[1] = fmaf(a0.y, v, mu_[1]);  v2_[1] = fmaf(a0.y, vv, v2_[1]);
                mu_[2] = fmaf(a0.z, v, mu_[2]);  v2_[2] = fmaf(a0.z, vv, v2_[2]);
                mu_[3] = fmaf(a0.w, v, mu_[3]);  v2_[3] = fmaf(a0.w, vv, v2_[3]);
                mu_[4] = fmaf(a1.x, v, mu_[4]);  v2_[4] = fmaf(a1.x, vv, v2_[4]);
                mu_[5] = fmaf(a1.y, v, mu_[5]);  v2_[5] = fmaf(a1.y, vv, v2_[5]);
                mu_[6] = fmaf(a1.z, v, mu_[6]);  v2_[6] = fmaf(a1.z, vv, v2_[6]);
                mu_[7] = fmaf(a1.w, v, mu_[7]);  v2_[7] = fmaf(a1.w, vv, v2_[7]);
            }
            #pragma unroll
            for (int k = 0; k < Kk; k++) {
                size_t idx = (((size_t)y * Bb + b) * Kk + k) * Dd + t;
                g_mupart[idx] = mu_[k];
                g_v2part[idx] = v2_[k];
            }
        }

        gbar();

        // ---- Reduce phase: this block reduces slot (b, k=y); thread owns d=t ----
        {
            int k = y;
            float S = 0.f;
            #pragma unroll
            for (int c = 0; c < NCHB; c++)
                S += g_Spart[((size_t)b * NCHB + c) * Kk + k];   // fixed order
            float denom = S + c_EPS;
            float s = S / denom;
            float slog = 0.f, sqwq = 0.f;
            {
                int d = t;
                float m = 0.f, v2 = 0.f;
                #pragma unroll
                for (int c = 0; c < NCHB; c++) {
                    size_t idx = (((size_t)c * Bb + b) * Kk + k) * Dd + d;
                    m  += g_mupart[idx];
                    v2 += g_v2part[idx];
                }
                m  /= denom;
                v2 /= denom;
                float sg = v2 - m * m * (2.f - s);
                if (it == NITER - 1) {
                    float sa = fmaxf(fabsf(sg), c_EPS);
                    out[(size_t)bk_ * Dd + d] = m + sa * noise_final[(size_t)bk_ * Dd + d];
                } else {
                    float w = 1.f / (sg * sg + c_EPS);
                    float q = g_q[(size_t)bk_ * Dd + d];
                    g_wq[(size_t)bk_ * Dd + d] = make_float2(w, q * w);
                    slog = logf(fabsf(sg) + c_EPS);
                    sqwq = q * q * w;
                }
            }
            if (it == NITER - 1) {
                float* ao = out + Bb * Kk * Dd + ((size_t)b * Kk + k) * Nn;
                float inv = 1.f / denom;
                for (int n = t; n < Nn; n += EMT)
                    ao[n] = g_attn[((size_t)b * Nn + n) * Kk + k] * inv;
            } else {
                #pragma unroll
                for (int o = 16; o; o >>= 1) {
                    slog += __shfl_xor_sync(0xffffffffu, slog, o);
                    sqwq += __shfl_xor_sync(0xffffffffu, sqwq, o);
                }
                if (lane == 0) { sh[0][warp] = slog; sh[1][warp] = sqwq; }
                __syncthreads();
                if (t == 0) {
                    float SL = 0.f, SQ = 0.f;
                    #pragma unroll
                    for (int w = 0; w < 16; w++) { SL += sh[0][w]; SQ += sh[1][w]; }
                    g_c1[bk_] = -0.5f * (float)Dd * c_LOG2PI - 0.5f * SL - 0.5f * SQ;
                    g_mixing[bk_] = s / (float)Nn;
                }
            }
        }

        if (it < NITER - 1) gbar();
    }
}

// ---------------- launcher ---------------------------------------------------
extern "C" void kernel_launch(void* const* d_in, const int* in_sizes, int n_in,
                              void* d_out, int out_size) {
    const float* embeddings = (const float*)d_in[0];
    const float* noise_init = (const float*)d_in[1];
    const float* noise_final= (const float*)d_in[2];
    const float* slots_mu   = (const float*)d_in[3];
    const float* slots_ls   = (const float*)d_in[4];
    const float* mixing     = (const float*)d_in[5];
    const float* Wk = (const float*)d_in[6];
    const float* bk = (const float*)d_in[7];
    const float* Wq = (const float*)d_in[8];
    const float* bq = (const float*)d_in[9];
    const float* Wv = (const float*)d_in[10];
    const float* bv = (const float*)d_in[11];
    const float* lng = (const float*)d_in[12];
    const float* lnb = (const float*)d_in[13];
    float* out = (float*)d_out;

    cudaFuncSetAttribute(mma_kv, cudaFuncAttributeMaxDynamicSharedMemorySize, MMA_SMEM);

    ln_split<<<Mtot, 128>>>(embeddings, lng, lnb);
    wt_split<<<dim3(32, 16), dim3(32, 8)>>>(Wk, Wv);
    init_slots_queries<<<Bb * Kk, 128>>>(noise_init, slots_mu, slots_ls, mixing, Wq, bq);
    mma_kv<<<dim3(Ntot / 128, Mtot / 128), 256, MMA_SMEM>>>(bk, bv);

    em_persist<<<dim3(Bb, NCHB), EMT>>>(noise_final, out);
}